// round 1
// baseline (speedup 1.0000x reference)
#include <cuda_runtime.h>
#include <math.h>

#define NHC 256
#define IC1 257
#define KW 5
#define BATCH 64
#define TMAX 4096
#define TOUT_MAX 2048

// Scratch (device globals -- no allocation allowed)
__device__ float g_bufL[BATCH * NHC * TOUT_MAX];
__device__ float g_bufR[BATCH * NHC * TOUT_MAX];
__device__ float g_bufH0[BATCH * NHC * TOUT_MAX];
__device__ float g_bufH1[BATCH * NHC * TOUT_MAX];
__device__ float g_captured[BATCH * NHC];

__device__ __forceinline__ int finish_depth(int n) {
    // depth at which N first reaches <= 1 (N updated before the check)
    #pragma unroll 1
    for (int dd = 0; dd < 12; dd++) {
        n = (n - 1) / 2 + 1;
        if (n <= 1) return dd;
    }
    return 11;
}

// conv1: OC=512 (threads), stride 2, K=5, pad 2. IC = 256 h-channels + depth channel.
// Writes l (oc<256, +bias) and r (oc>=256, +bias, relu, masked by N_new).
__global__ __launch_bounds__(512) void conv1_kernel(
    const float* __restrict__ h_ext, const int* __restrict__ N0,
    const float* __restrict__ w1, const float* __restrict__ b1,
    int d, int T_in, int T_out, float dval)
{
    const int b = blockIdx.y;
    const int tile = blockIdx.x;
    const int oc = threadIdx.x;              // 0..511
    const int t0 = tile * 16;
    const int pstart = 2 * t0 - 2;

    const float* hin = (d == 0) ? h_ext : (((d - 1) & 1) ? g_bufH1 : g_bufH0);
    const int n0 = N0[b];
    const int Ncur = (n0 + (1 << d) - 1) >> d;          // ceil(n0 / 2^d)
    const int Nnew = (n0 + (2 << d) - 1) >> (d + 1);    // ceil(n0 / 2^(d+1))

    __shared__ float sm[32][36];   // 36*4=144B rows -> 16B aligned

    float acc[16];
    {
        float bias = b1[oc];
        #pragma unroll
        for (int t = 0; t < 16; t++) acc[t] = bias;
    }

    // depth channel (ic = 256): constant dval, seq-masked
    {
        float wd[5];
        #pragma unroll
        for (int k = 0; k < 5; k++) wd[k] = w1[((size_t)oc * IC1 + 256) * KW + k];
        #pragma unroll
        for (int t = 0; t < 16; t++) {
            #pragma unroll
            for (int k = 0; k < 5; k++) {
                int p = pstart + 2 * t + k;
                if (p >= 0 && p < Ncur) acc[t] += dval * wd[k];
            }
        }
    }

    for (int icc = 0; icc < NHC; icc += 32) {
        __syncthreads();
        for (int idx = threadIdx.x; idx < 32 * 36; idx += 512) {
            int ic = idx / 36, j = idx - ic * 36;
            int p = pstart + j;
            float v = 0.f;
            if (p >= 0 && p < Ncur)
                v = hin[((size_t)(b * NHC + icc + ic)) * T_in + p];
            sm[ic][j] = v;
        }
        __syncthreads();

        #pragma unroll 2
        for (int ic = 0; ic < 32; ic++) {
            float w[5];
            const float* wp = &w1[((size_t)oc * IC1 + (icc + ic)) * KW];
            #pragma unroll
            for (int k = 0; k < 5; k++) w[k] = wp[k];

            float x[36];
            const float4* sp = reinterpret_cast<const float4*>(&sm[ic][0]);
            #pragma unroll
            for (int q = 0; q < 9; q++) {
                float4 v4 = sp[q];
                x[4*q] = v4.x; x[4*q+1] = v4.y; x[4*q+2] = v4.z; x[4*q+3] = v4.w;
            }
            #pragma unroll
            for (int t = 0; t < 16; t++) {
                acc[t] += w[0]*x[2*t] + w[1]*x[2*t+1] + w[2]*x[2*t+2]
                        + w[3]*x[2*t+3] + w[4]*x[2*t+4];
            }
        }
    }

    #pragma unroll
    for (int t = 0; t < 16; t++) {
        int tg = t0 + t;
        if (tg < T_out) {
            if (oc < NHC) {
                g_bufL[((size_t)(b * NHC + oc)) * T_out + tg] = acc[t];
            } else {
                float v = fmaxf(acc[t], 0.f);
                if (tg >= Nnew) v = 0.f;
                g_bufR[((size_t)(b * NHC + oc - NHC)) * T_out + tg] = v;
            }
        }
    }
}

// conv2: 256x256, stride 1, K=5, pad 2 on r; h = relu(l + conv2(r) + b2); captures h[:,:,0]
__global__ __launch_bounds__(256) void conv2_kernel(
    const int* __restrict__ N0, const float* __restrict__ w2,
    const float* __restrict__ b2, int d, int T_out)
{
    const int b = blockIdx.y;
    const int tile = blockIdx.x;
    const int oc = threadIdx.x;              // 0..255
    const int t0 = tile * 16;
    const int pstart = t0 - 2;
    float* hout = (d & 1) ? g_bufH1 : g_bufH0;

    __shared__ float sm[32][20];   // 80B rows -> 16B aligned

    float acc[16];
    {
        float bias = b2[oc];
        #pragma unroll
        for (int t = 0; t < 16; t++) acc[t] = bias;
    }

    for (int icc = 0; icc < NHC; icc += 32) {
        __syncthreads();
        for (int idx = threadIdx.x; idx < 32 * 20; idx += 256) {
            int ic = idx / 20, j = idx - ic * 20;
            int p = pstart + j;
            float v = 0.f;
            if (p >= 0 && p < T_out)
                v = g_bufR[((size_t)(b * NHC + icc + ic)) * T_out + p];
            sm[ic][j] = v;
        }
        __syncthreads();

        #pragma unroll 2
        for (int ic = 0; ic < 32; ic++) {
            float w[5];
            const float* wp = &w2[((size_t)oc * NHC + (icc + ic)) * KW];
            #pragma unroll
            for (int k = 0; k < 5; k++) w[k] = wp[k];

            float x[20];
            const float4* sp = reinterpret_cast<const float4*>(&sm[ic][0]);
            #pragma unroll
            for (int q = 0; q < 5; q++) {
                float4 v4 = sp[q];
                x[4*q] = v4.x; x[4*q+1] = v4.y; x[4*q+2] = v4.z; x[4*q+3] = v4.w;
            }
            #pragma unroll
            for (int t = 0; t < 16; t++) {
                acc[t] += w[0]*x[t] + w[1]*x[t+1] + w[2]*x[t+2]
                        + w[3]*x[t+3] + w[4]*x[t+4];
            }
        }
    }

    #pragma unroll
    for (int t = 0; t < 16; t++) {
        int tg = t0 + t;
        if (tg < T_out) {
            size_t off = ((size_t)(b * NHC + oc)) * T_out + tg;
            float v = fmaxf(acc[t] + g_bufL[off], 0.f);
            hout[off] = v;
            if (tg == 0) {
                if (finish_depth(N0[b]) == d)
                    g_captured[b * NHC + oc] = v;
            }
        }
    }
}

// Stable counting sort by finish depth, then gather captured rows.
__global__ void finalize_kernel(const int* __restrict__ N0, float* __restrict__ out)
{
    __shared__ int order[BATCH];
    if (threadIdx.x == 0) {
        int fd[BATCH];
        int cnt[13];
        for (int i = 0; i < 13; i++) cnt[i] = 0;
        for (int bb = 0; bb < BATCH; bb++) {
            fd[bb] = finish_depth(N0[bb]);
            cnt[fd[bb]]++;
        }
        int pos[13];
        int run = 0;
        for (int i = 0; i < 13; i++) { pos[i] = run; run += cnt[i]; }
        for (int bb = 0; bb < BATCH; bb++) {
            order[pos[fd[bb]]++] = bb;
        }
    }
    __syncthreads();
    for (int i = threadIdx.x; i < BATCH * NHC; i += blockDim.x) {
        int row = i >> 8, c = i & 255;
        out[i] = g_captured[order[row] * NHC + c];
    }
}

extern "C" void kernel_launch(void* const* d_in, const int* in_sizes, int n_in,
                              void* d_out, int out_size)
{
    const float* h  = (const float*)d_in[0];
    const int*   N0 = (const int*)d_in[1];
    const float* w1 = (const float*)d_in[2];
    const float* b1 = (const float*)d_in[3];
    const float* w2 = (const float*)d_in[4];
    const float* b2 = (const float*)d_in[5];

    for (int d = 0; d < 12; d++) {
        int T_in  = TMAX >> d;
        int T_out = T_in >> 1;
        int tiles = (T_out + 15) / 16;
        float dval = (float)log1p((double)d);
        conv1_kernel<<<dim3(tiles, BATCH), 512>>>(h, N0, w1, b1, d, T_in, T_out, dval);
        conv2_kernel<<<dim3(tiles, BATCH), 256>>>(N0, w2, b2, d, T_out);
    }
    finalize_kernel<<<1, 256>>>(N0, (float*)d_out);
}

// round 2
// speedup vs baseline: 2.6008x; 2.6008x over previous
#include <cuda_runtime.h>
#include <math.h>

#define NHC 256
#define OC1 512
#define IC1 257
#define KW 5
#define BATCH 64
#define TMAX 4096
#define TOUT_MAX 2048

// Scratch (device globals -- no allocation allowed)
__device__ float g_bufL[BATCH * NHC * TOUT_MAX];
__device__ float g_bufR[BATCH * NHC * TOUT_MAX];
__device__ float g_bufH0[BATCH * NHC * TOUT_MAX];
__device__ float g_bufH1[BATCH * NHC * TOUT_MAX];
__device__ float g_captured[BATCH * NHC];
// Transposed weights: wT1[(ic*KW+k)*OC1 + oc], wT2[(ic*KW+k)*NHC + oc]
__device__ float g_w1T[IC1 * KW * OC1];
__device__ float g_w2T[NHC * KW * NHC];

__device__ __forceinline__ int finish_depth(int n) {
    #pragma unroll 1
    for (int dd = 0; dd < 12; dd++) {
        n = (n - 1) / 2 + 1;
        if (n <= 1) return dd;
    }
    return 11;
}

// ---- weight transpose kernels (run once per call; cheap) ----
__global__ void transpose_w1_kernel(const float* __restrict__ w1) {
    int idx = blockIdx.x * blockDim.x + threadIdx.x;   // over OC1*IC1*KW
    int total = OC1 * IC1 * KW;
    if (idx < total) {
        int k  = idx % KW;
        int ic = (idx / KW) % IC1;
        int oc = idx / (KW * IC1);
        g_w1T[(ic * KW + k) * OC1 + oc] = w1[idx];
    }
}
__global__ void transpose_w2_kernel(const float* __restrict__ w2) {
    int idx = blockIdx.x * blockDim.x + threadIdx.x;   // over NHC*NHC*KW
    int total = NHC * NHC * KW;
    if (idx < total) {
        int k  = idx % KW;
        int ic = (idx / KW) % NHC;
        int oc = idx / (KW * NHC);
        g_w2T[(ic * KW + k) * NHC + oc] = w2[idx];
    }
}

// conv1: OC=512 (threads), stride 2, K=5, pad 2. IC = 256 h-channels + depth channel.
__global__ __launch_bounds__(512) void conv1_kernel(
    const float* __restrict__ h_ext, const int* __restrict__ N0,
    const float* __restrict__ b1,
    int d, int T_in, int T_out, float dval)
{
    const int b = blockIdx.y;
    const int tile = blockIdx.x;
    const int oc = threadIdx.x;              // 0..511
    const int t0 = tile * 16;
    const int pstart = 2 * t0 - 2;

    const float* hin = (d == 0) ? h_ext : (((d - 1) & 1) ? g_bufH1 : g_bufH0);
    const int n0 = N0[b];
    const int Ncur = (n0 + (1 << d) - 1) >> d;
    const int Nnew = (n0 + (2 << d) - 1) >> (d + 1);

    __shared__ float sm[32][36];

    float acc[16];
    {
        float bias = b1[oc];
        #pragma unroll
        for (int t = 0; t < 16; t++) acc[t] = bias;
    }

    // depth channel (ic = 256): constant dval, seq-masked. Coalesced wT loads.
    {
        float wd[5];
        #pragma unroll
        for (int k = 0; k < 5; k++) wd[k] = g_w1T[(256 * KW + k) * OC1 + oc];
        #pragma unroll
        for (int t = 0; t < 16; t++) {
            #pragma unroll
            for (int k = 0; k < 5; k++) {
                int p = pstart + 2 * t + k;
                if (p >= 0 && p < Ncur) acc[t] += dval * wd[k];
            }
        }
    }

    for (int icc = 0; icc < NHC; icc += 32) {
        __syncthreads();
        for (int idx = threadIdx.x; idx < 32 * 36; idx += 512) {
            int ic = idx / 36, j = idx - ic * 36;
            int p = pstart + j;
            float v = 0.f;
            if (p >= 0 && p < Ncur)
                v = hin[((size_t)(b * NHC + icc + ic)) * T_in + p];
            sm[ic][j] = v;
        }
        __syncthreads();

        #pragma unroll 4
        for (int ic = 0; ic < 32; ic++) {
            float w[5];
            const float* wp = &g_w1T[((icc + ic) * KW) * OC1 + oc];
            #pragma unroll
            for (int k = 0; k < 5; k++) w[k] = __ldg(wp + k * OC1);

            float x[36];
            const float4* sp = reinterpret_cast<const float4*>(&sm[ic][0]);
            #pragma unroll
            for (int q = 0; q < 9; q++) {
                float4 v4 = sp[q];
                x[4*q] = v4.x; x[4*q+1] = v4.y; x[4*q+2] = v4.z; x[4*q+3] = v4.w;
            }
            #pragma unroll
            for (int t = 0; t < 16; t++) {
                acc[t] += w[0]*x[2*t] + w[1]*x[2*t+1] + w[2]*x[2*t+2]
                        + w[3]*x[2*t+3] + w[4]*x[2*t+4];
            }
        }
    }

    #pragma unroll
    for (int t = 0; t < 16; t++) {
        int tg = t0 + t;
        if (tg < T_out) {
            if (oc < NHC) {
                g_bufL[((size_t)(b * NHC + oc)) * T_out + tg] = acc[t];
            } else {
                float v = fmaxf(acc[t], 0.f);
                if (tg >= Nnew) v = 0.f;
                g_bufR[((size_t)(b * NHC + oc - NHC)) * T_out + tg] = v;
            }
        }
    }
}

// conv2: 256x256, stride 1, K=5, pad 2 on r; h = relu(l + conv2(r) + b2); captures h[:,:,0]
__global__ __launch_bounds__(256) void conv2_kernel(
    const int* __restrict__ N0,
    const float* __restrict__ b2, int d, int T_out)
{
    const int b = blockIdx.y;
    const int tile = blockIdx.x;
    const int oc = threadIdx.x;              // 0..255
    const int t0 = tile * 16;
    const int pstart = t0 - 2;
    float* hout = (d & 1) ? g_bufH1 : g_bufH0;

    __shared__ float sm[32][20];

    float acc[16];
    {
        float bias = b2[oc];
        #pragma unroll
        for (int t = 0; t < 16; t++) acc[t] = bias;
    }

    for (int icc = 0; icc < NHC; icc += 32) {
        __syncthreads();
        for (int idx = threadIdx.x; idx < 32 * 20; idx += 256) {
            int ic = idx / 20, j = idx - ic * 20;
            int p = pstart + j;
            float v = 0.f;
            if (p >= 0 && p < T_out)
                v = g_bufR[((size_t)(b * NHC + icc + ic)) * T_out + p];
            sm[ic][j] = v;
        }
        __syncthreads();

        #pragma unroll 4
        for (int ic = 0; ic < 32; ic++) {
            float w[5];
            const float* wp = &g_w2T[((icc + ic) * KW) * NHC + oc];
            #pragma unroll
            for (int k = 0; k < 5; k++) w[k] = __ldg(wp + k * NHC);

            float x[20];
            const float4* sp = reinterpret_cast<const float4*>(&sm[ic][0]);
            #pragma unroll
            for (int q = 0; q < 5; q++) {
                float4 v4 = sp[q];
                x[4*q] = v4.x; x[4*q+1] = v4.y; x[4*q+2] = v4.z; x[4*q+3] = v4.w;
            }
            #pragma unroll
            for (int t = 0; t < 16; t++) {
                acc[t] += w[0]*x[t] + w[1]*x[t+1] + w[2]*x[t+2]
                        + w[3]*x[t+3] + w[4]*x[t+4];
            }
        }
    }

    #pragma unroll
    for (int t = 0; t < 16; t++) {
        int tg = t0 + t;
        if (tg < T_out) {
            size_t off = ((size_t)(b * NHC + oc)) * T_out + tg;
            float v = fmaxf(acc[t] + g_bufL[off], 0.f);
            hout[off] = v;
            if (tg == 0) {
                if (finish_depth(N0[b]) == d)
                    g_captured[b * NHC + oc] = v;
            }
        }
    }
}

// Stable counting sort by finish depth, then gather captured rows.
__global__ void finalize_kernel(const int* __restrict__ N0, float* __restrict__ out)
{
    __shared__ int order[BATCH];
    if (threadIdx.x == 0) {
        int fd[BATCH];
        int cnt[13];
        for (int i = 0; i < 13; i++) cnt[i] = 0;
        for (int bb = 0; bb < BATCH; bb++) {
            fd[bb] = finish_depth(N0[bb]);
            cnt[fd[bb]]++;
        }
        int pos[13];
        int run = 0;
        for (int i = 0; i < 13; i++) { pos[i] = run; run += cnt[i]; }
        for (int bb = 0; bb < BATCH; bb++) {
            order[pos[fd[bb]]++] = bb;
        }
    }
    __syncthreads();
    for (int i = threadIdx.x; i < BATCH * NHC; i += blockDim.x) {
        int row = i >> 8, c = i & 255;
        out[i] = g_captured[order[row] * NHC + c];
    }
}

extern "C" void kernel_launch(void* const* d_in, const int* in_sizes, int n_in,
                              void* d_out, int out_size)
{
    const float* h  = (const float*)d_in[0];
    const int*   N0 = (const int*)d_in[1];
    const float* w1 = (const float*)d_in[2];
    const float* b1 = (const float*)d_in[3];
    const float* w2 = (const float*)d_in[4];
    const float* b2 = (const float*)d_in[5];

    {
        int tot1 = OC1 * IC1 * KW;
        transpose_w1_kernel<<<(tot1 + 255) / 256, 256>>>(w1);
        int tot2 = NHC * NHC * KW;
        transpose_w2_kernel<<<(tot2 + 255) / 256, 256>>>(w2);
    }

    for (int d = 0; d < 12; d++) {
        int T_in  = TMAX >> d;
        int T_out = T_in >> 1;
        int tiles = (T_out + 15) / 16;
        float dval = (float)log1p((double)d);
        conv1_kernel<<<dim3(tiles, BATCH), 512>>>(h, N0, b1, d, T_in, T_out, dval);
        conv2_kernel<<<dim3(tiles, BATCH), 256>>>(N0, b2, d, T_out);
    }
    finalize_kernel<<<1, 256>>>(N0, (float*)d_out);
}